// round 2
// baseline (speedup 1.0000x reference)
#include <cuda_runtime.h>

#define NN 100000
#define EE 640000
#define GG 64
#define BN_EPS 1e-5f
#define SLOPE 0.01f
#define NB_SCAN 98   // ceil(100000/1024)

// ---------------- scratch (static device allocations; no runtime alloc) -----
__device__ int   g_deg[NN];
__device__ float g_dinv[NN];
__device__ int   g_cnt[NN];
__device__ int   g_rowptr[NN + 1];
__device__ int   g_cursor[NN];
__device__ int   g_bsums[128];
__device__ int   g_boffs[130];
__device__ int   g_csr_src[EE];
__device__ float g_csr_w[EE];
__device__ float g_T1[NN * 128];
__device__ float g_T2[NN * 128];
__device__ float g_H1[NN * 64];
__device__ float g_H2[NN * 32];
__device__ float g_H3[NN * 16];
__device__ float g_pooled[GG * 16];
__device__ int   g_pcnt[GG];

// ---------------- init ------------------------------------------------------
__global__ void k_zero() {
    int i = blockIdx.x * blockDim.x + threadIdx.x;
    if (i < NN) { g_deg[i] = 0; g_cnt[i] = 0; g_cursor[i] = 0; }
    if (i < GG * 16) g_pooled[i] = 0.f;
    if (i < GG) g_pcnt[i] = 0;
}

// degree over src (non-loop) + per-dst edge counts for CSR
__global__ void k_count(const int* __restrict__ ei) {
    int e = blockIdx.x * blockDim.x + threadIdx.x;
    if (e >= EE) return;
    int s = ei[e], d = ei[EE + e];
    if (s != d) {
        atomicAdd(&g_deg[s], 1);
        atomicAdd(&g_cnt[d], 1);
    }
}

__global__ void k_dinv() {
    int i = blockIdx.x * blockDim.x + threadIdx.x;
    if (i < NN) g_dinv[i] = (g_deg[i] > 0) ? rsqrtf((float)g_deg[i]) : 0.f;
}

// ---------------- exclusive scan of g_cnt -> g_rowptr ----------------------
__global__ void k_scan1() {
    __shared__ int sm[1024];
    int t = threadIdx.x;
    int i = blockIdx.x * 1024 + t;
    int v = (i < NN) ? g_cnt[i] : 0;
    sm[t] = v;
    __syncthreads();
    for (int off = 1; off < 1024; off <<= 1) {
        int add = (t >= off) ? sm[t - off] : 0;
        __syncthreads();
        sm[t] += add;
        __syncthreads();
    }
    if (i < NN) g_rowptr[i] = sm[t] - v;   // exclusive within block
    if (t == 1023) g_bsums[blockIdx.x] = sm[1023];
}

__global__ void k_scan2(int nb) {
    if (threadIdx.x == 0) {
        int run = 0;
        for (int i = 0; i < nb; i++) { int v = g_bsums[i]; g_boffs[i] = run; run += v; }
        g_boffs[nb] = run;
    }
}

__global__ void k_scan3(int nb) {
    int i = blockIdx.x * blockDim.x + threadIdx.x;
    if (i < NN) g_rowptr[i] += g_boffs[i >> 10];
    if (i == 0) g_rowptr[NN] = g_boffs[nb];
}

// scatter edges into CSR (by dst), storing src and normalized weight
__global__ void k_fill(const int* __restrict__ ei) {
    int e = blockIdx.x * blockDim.x + threadIdx.x;
    if (e >= EE) return;
    int s = ei[e], d = ei[EE + e];
    if (s == d) return;
    float wv = -g_dinv[s] * g_dinv[d];
    int pos = g_rowptr[d] + atomicAdd(&g_cursor[d], 1);
    g_csr_src[pos] = s;
    g_csr_w[pos]   = wv;
}

// ---------------- sparse propagation: out = scale * (L_hat @ X) [- sub] ----
// one warp per node, lanes split features (float4 / float2 / float)
template <int F>
__global__ void k_prop(const float* __restrict__ X, const float* __restrict__ sub,
                       float scale, float* __restrict__ out) {
    int gw   = (blockIdx.x * blockDim.x + threadIdx.x) >> 5;
    int lane = threadIdx.x & 31;
    if (gw >= NN) return;
    int beg = g_rowptr[gw], end = g_rowptr[gw + 1];
    constexpr int VEC = F / 32;
    float acc[VEC];
#pragma unroll
    for (int v = 0; v < VEC; v++) acc[v] = 0.f;

    for (int idx = beg; idx < end; idx++) {
        int s    = g_csr_src[idx];     // broadcast load
        float wv = g_csr_w[idx];
        const float* xp = X + s * F + lane * VEC;
        if constexpr (VEC == 4) {
            float4 xv = *reinterpret_cast<const float4*>(xp);
            acc[0] += wv * xv.x; acc[1] += wv * xv.y;
            acc[2] += wv * xv.z; acc[3] += wv * xv.w;
        } else if constexpr (VEC == 2) {
            float2 xv = *reinterpret_cast<const float2*>(xp);
            acc[0] += wv * xv.x; acc[1] += wv * xv.y;
        } else {
            acc[0] += wv * xp[0];
        }
    }

    float* op = out + gw * F + lane * VEC;
    if (sub) {
        const float* sp = sub + gw * F + lane * VEC;
#pragma unroll
        for (int v = 0; v < VEC; v++) op[v] = scale * acc[v] - sp[v];
    } else {
#pragma unroll
        for (int v = 0; v < VEC; v++) op[v] = scale * acc[v];
    }
}

// ---------------- fused 3-way GEMM + bias + BN + leakyReLU ------------------
// out[r,o] = lrelu(BN( H@W0 + T1@W1 + T2@W2 + b ))
// thread tile: 4 rows x 4 cols; W loaded as float4 (coalesced, L1-resident)
template <int Fin, int Fout>
__global__ void k_gemm3(const float* __restrict__ H,  const float* __restrict__ T1,
                        const float* __restrict__ T2, const float* __restrict__ W,
                        const float* __restrict__ bias, const float* __restrict__ gam,
                        const float* __restrict__ bet,  const float* __restrict__ mu,
                        const float* __restrict__ var,  float* __restrict__ out) {
    constexpr int OT   = Fout / 4;
    constexpr int RT   = 256 / OT;
    constexpr int ROWS = RT * 4;
    int ot = threadIdx.x % OT;
    int rt = threadIdx.x / OT;
    int r0 = blockIdx.x * ROWS + rt * 4;
    int o0 = ot * 4;

    int rr[4];
#pragma unroll
    for (int j = 0; j < 4; j++) rr[j] = min(r0 + j, NN - 1);

    const float* W0 = W;
    const float* W1 = W + Fin * Fout;
    const float* W2 = W + 2 * Fin * Fout;

    float acc[4][4];
#pragma unroll
    for (int j = 0; j < 4; j++)
#pragma unroll
        for (int c = 0; c < 4; c++) acc[j][c] = 0.f;

#pragma unroll 4
    for (int f = 0; f < Fin; f++) {
        float4 w0 = *reinterpret_cast<const float4*>(W0 + f * Fout + o0);
        float4 w1 = *reinterpret_cast<const float4*>(W1 + f * Fout + o0);
        float4 w2 = *reinterpret_cast<const float4*>(W2 + f * Fout + o0);
#pragma unroll
        for (int j = 0; j < 4; j++) {
            float h = __ldg(H  + rr[j] * Fin + f);
            float a = __ldg(T1 + rr[j] * Fin + f);
            float b = __ldg(T2 + rr[j] * Fin + f);
            acc[j][0] += h * w0.x + a * w1.x + b * w2.x;
            acc[j][1] += h * w0.y + a * w1.y + b * w2.y;
            acc[j][2] += h * w0.z + a * w1.z + b * w2.z;
            acc[j][3] += h * w0.w + a * w1.w + b * w2.w;
        }
    }

    float sc[4], sh[4];
#pragma unroll
    for (int c = 0; c < 4; c++) {
        int o = o0 + c;
        float s = gam[o] * rsqrtf(var[o] + BN_EPS);
        sc[c] = s;
        sh[c] = bet[o] - mu[o] * s + bias[o] * s;
    }
#pragma unroll
    for (int j = 0; j < 4; j++) {
        int row = r0 + j;
        if (row >= NN) continue;
#pragma unroll
        for (int c = 0; c < 4; c++) {
            float y = acc[j][c] * sc[c] + sh[c];
            y = (y > 0.f) ? y : SLOPE * y;
            out[row * Fout + o0 + c] = y;
        }
    }
}

// ---------------- per-graph mean pool (two-stage: smem, then global) -------
#define PNODES 1024
__global__ void k_pool(const float* __restrict__ H, const int* __restrict__ batch) {
    __shared__ float ssum[GG * 16];
    __shared__ int   scnt[GG];
    for (int i = threadIdx.x; i < GG * 16; i += 256) ssum[i] = 0.f;
    for (int i = threadIdx.x; i < GG; i += 256) scnt[i] = 0;
    __syncthreads();

    int f   = threadIdx.x & 15;
    int sub = threadIdx.x >> 4;     // 0..15
    int base = blockIdx.x * PNODES;
    for (int n = sub; n < PNODES; n += 16) {
        int node = base + n;
        if (node >= NN) break;
        int b = batch[node];
        atomicAdd(&ssum[b * 16 + f], H[node * 16 + f]);
        if (f == 0) atomicAdd(&scnt[b], 1);
    }
    __syncthreads();
    for (int i = threadIdx.x; i < GG * 16; i += 256) atomicAdd(&g_pooled[i], ssum[i]);
    for (int i = threadIdx.x; i < GG; i += 256) atomicAdd(&g_pcnt[i], scnt[i]);
}

__global__ void k_final(const float* __restrict__ lw, const float* __restrict__ lb,
                        float* __restrict__ out) {
    int t = threadIdx.x;
    if (t >= GG * 2) return;
    int g = t >> 1, c = t & 1;
    float inv = 1.f / fmaxf((float)g_pcnt[g], 1.f);
    float s = 0.f;
#pragma unroll
    for (int f = 0; f < 16; f++) s += g_pooled[g * 16 + f] * lw[c * 16 + f];
    out[t] = s * inv + lb[c];
}

// ---------------- launch ----------------------------------------------------
extern "C" void kernel_launch(void* const* d_in, const int* in_sizes, int n_in,
                              void* d_out, int out_size) {
    const float* x     = (const float*)d_in[0];
    const int*   ei    = (const int*)  d_in[1];
    const int*   batch = (const int*)  d_in[2];
    const float* W1 = (const float*)d_in[3];
    const float* b1 = (const float*)d_in[4];
    const float* g1 = (const float*)d_in[5];
    const float* be1= (const float*)d_in[6];
    const float* m1 = (const float*)d_in[7];
    const float* v1 = (const float*)d_in[8];
    const float* W2 = (const float*)d_in[9];
    const float* b2 = (const float*)d_in[10];
    const float* g2 = (const float*)d_in[11];
    const float* be2= (const float*)d_in[12];
    const float* m2 = (const float*)d_in[13];
    const float* v2 = (const float*)d_in[14];
    const float* W3 = (const float*)d_in[15];
    const float* b3 = (const float*)d_in[16];
    const float* g3 = (const float*)d_in[17];
    const float* be3= (const float*)d_in[18];
    const float* m3 = (const float*)d_in[19];
    const float* v3 = (const float*)d_in[20];
    const float* lw = (const float*)d_in[21];
    const float* lb = (const float*)d_in[22];
    float* out = (float*)d_out;

    float *T1, *T2, *H1, *H2, *H3;
    cudaGetSymbolAddress((void**)&T1, g_T1);
    cudaGetSymbolAddress((void**)&T2, g_T2);
    cudaGetSymbolAddress((void**)&H1, g_H1);
    cudaGetSymbolAddress((void**)&H2, g_H2);
    cudaGetSymbolAddress((void**)&H3, g_H3);

    const int TB = 256;
    // --- graph normalization + CSR build ---
    k_zero <<<(NN + TB - 1) / TB, TB>>>();
    k_count<<<(EE + TB - 1) / TB, TB>>>(ei);
    k_dinv <<<(NN + TB - 1) / TB, TB>>>();
    k_scan1<<<NB_SCAN, 1024>>>();
    k_scan2<<<1, 32>>>(NB_SCAN);
    k_scan3<<<(NN + TB - 1) / TB, TB>>>(NB_SCAN);
    k_fill <<<(EE + TB - 1) / TB, TB>>>(ei);

    int prop_grid = (NN * 32 + TB - 1) / TB;   // one warp per node

    // --- layer 1: F 128 -> 64 ---
    k_prop<128><<<prop_grid, TB>>>(x,  nullptr, 1.f, T1);
    k_prop<128><<<prop_grid, TB>>>(T1, x,       2.f, T2);
    k_gemm3<128, 64><<<(NN + 63) / 64, 256>>>(x, T1, T2, W1, b1, g1, be1, m1, v1, H1);

    // --- layer 2: F 64 -> 32 ---
    k_prop<64><<<prop_grid, TB>>>(H1, nullptr, 1.f, T1);
    k_prop<64><<<prop_grid, TB>>>(T1, H1,      2.f, T2);
    k_gemm3<64, 32><<<(NN + 127) / 128, 256>>>(H1, T1, T2, W2, b2, g2, be2, m2, v2, H2);

    // --- layer 3: F 32 -> 16 ---
    k_prop<32><<<prop_grid, TB>>>(H2, nullptr, 1.f, T1);
    k_prop<32><<<prop_grid, TB>>>(T1, H2,      2.f, T2);
    k_gemm3<32, 16><<<(NN + 255) / 256, 256>>>(H2, T1, T2, W3, b3, g3, be3, m3, v3, H3);

    // --- pool + linear head ---
    k_pool <<<(NN + PNODES - 1) / PNODES, 256>>>(H3, batch);
    k_final<<<1, 128>>>(lw, lb, out);
}

// round 3
// speedup vs baseline: 1.2659x; 1.2659x over previous
#include <cuda_runtime.h>

#define NN 100000
#define EE 640000
#define GG 64
#define BN_EPS 1e-5f
#define SLOPE 0.01f
#define NB_SCAN 98   // ceil(100000/1024)

// ---------------- scratch (static device buffers) ---------------------------
__device__ int   g_deg[NN];
__device__ float g_dinv[NN];
__device__ int   g_cnt[NN];
__device__ int   g_rowptr[NN + 1];
__device__ int   g_cursor[NN];
__device__ int   g_bsums[128];
__device__ int   g_boffs[130];
__device__ int   g_csr_src[EE];
__device__ float g_csr_w[EE];

__device__ __align__(16) float g_Z0[NN * 64];
__device__ __align__(16) float g_Z1[NN * 64];
__device__ __align__(16) float g_Z2[NN * 64];
__device__ __align__(16) float g_S [NN * 64];
__device__ __align__(16) float g_H1[NN * 64];
__device__ __align__(16) float g_H2[NN * 32];
__device__ __align__(16) float g_H3[NN * 16];

__device__ __align__(16) float g_Wd1[128 * 64];
__device__ __align__(16) float g_Wd2[64 * 32];
__device__ __align__(16) float g_Wd3[32 * 16];
__device__ __align__(16) float g_sc1[64], g_sh1[64];
__device__ __align__(16) float g_sc2[32], g_sh2[32];
__device__ __align__(16) float g_sc3[16], g_sh3[16];

__device__ float g_pooled[GG * 16];
__device__ int   g_pcnt[GG];

// ---------------- f32x2 packed helpers -------------------------------------
__device__ __forceinline__ unsigned long long ffma2(unsigned long long a,
                                                    unsigned long long b,
                                                    unsigned long long c) {
    unsigned long long d;
    asm("fma.rn.f32x2 %0, %1, %2, %3;" : "=l"(d) : "l"(a), "l"(b), "l"(c));
    return d;
}
__device__ __forceinline__ unsigned long long dup2(float h) {
    unsigned long long r;
    unsigned hi = __float_as_uint(h);
    asm("mov.b64 %0, {%1, %1};" : "=l"(r) : "r"(hi));
    return r;
}

// ---------------- init ------------------------------------------------------
__global__ void k_zero() {
    int i = blockIdx.x * blockDim.x + threadIdx.x;
    if (i < NN) { g_deg[i] = 0; g_cnt[i] = 0; g_cursor[i] = 0; }
    if (i < GG * 16) g_pooled[i] = 0.f;
    if (i < GG) g_pcnt[i] = 0;
}

__global__ void k_count(const int* __restrict__ ei) {
    int e = blockIdx.x * blockDim.x + threadIdx.x;
    if (e >= EE) return;
    int s = ei[e], d = ei[EE + e];
    if (s != d) {
        atomicAdd(&g_deg[s], 1);
        atomicAdd(&g_cnt[d], 1);
    }
}

__global__ void k_dinv() {
    int i = blockIdx.x * blockDim.x + threadIdx.x;
    if (i < NN) g_dinv[i] = (g_deg[i] > 0) ? rsqrtf((float)g_deg[i]) : 0.f;
}

// ---------------- exclusive scan of g_cnt -> g_rowptr ----------------------
__global__ void k_scan1() {
    __shared__ int sm[1024];
    int t = threadIdx.x;
    int i = blockIdx.x * 1024 + t;
    int v = (i < NN) ? g_cnt[i] : 0;
    sm[t] = v;
    __syncthreads();
    for (int off = 1; off < 1024; off <<= 1) {
        int add = (t >= off) ? sm[t - off] : 0;
        __syncthreads();
        sm[t] += add;
        __syncthreads();
    }
    if (i < NN) g_rowptr[i] = sm[t] - v;
    if (t == 1023) g_bsums[blockIdx.x] = sm[1023];
}

__global__ void k_scan2(int nb) {
    if (threadIdx.x == 0) {
        int run = 0;
        for (int i = 0; i < nb; i++) { int v = g_bsums[i]; g_boffs[i] = run; run += v; }
        g_boffs[nb] = run;
    }
}

__global__ void k_scan3(int nb) {
    int i = blockIdx.x * blockDim.x + threadIdx.x;
    if (i < NN) g_rowptr[i] += g_boffs[i >> 10];
    if (i == 0) g_rowptr[NN] = g_boffs[nb];
}

__global__ void k_fill(const int* __restrict__ ei) {
    int e = blockIdx.x * blockDim.x + threadIdx.x;
    if (e >= EE) return;
    int s = ei[e], d = ei[EE + e];
    if (s == d) return;
    float wv = -g_dinv[s] * g_dinv[d];
    int pos = g_rowptr[d] + atomicAdd(&g_cursor[d], 1);
    g_csr_src[pos] = s;
    g_csr_w[pos]   = wv;
}

// ---------------- prep: Wd = W0 - W2 per layer; BN affine fold -------------
__global__ void k_prep(const float* __restrict__ W1, const float* __restrict__ W2,
                       const float* __restrict__ W3,
                       const float* __restrict__ b1, const float* __restrict__ gg1,
                       const float* __restrict__ be1, const float* __restrict__ m1,
                       const float* __restrict__ v1,
                       const float* __restrict__ b2, const float* __restrict__ gg2,
                       const float* __restrict__ be2, const float* __restrict__ m2,
                       const float* __restrict__ v2,
                       const float* __restrict__ b3, const float* __restrict__ gg3,
                       const float* __restrict__ be3, const float* __restrict__ m3,
                       const float* __restrict__ v3) {
    int i = blockIdx.x * blockDim.x + threadIdx.x;
    if (i < 8192) {                 // 128*64
        g_Wd1[i] = W1[i] - W1[2 * 8192 + i];
    } else if (i < 8192 + 2048) {   // 64*32
        int j = i - 8192;
        g_Wd2[j] = W2[j] - W2[2 * 2048 + j];
    } else if (i < 8192 + 2048 + 512) {  // 32*16
        int j = i - 8192 - 2048;
        g_Wd3[j] = W3[j] - W3[2 * 512 + j];
    } else if (i < 8192 + 2048 + 512 + 64) {
        int o = i - (8192 + 2048 + 512);
        float s = gg1[o] * rsqrtf(v1[o] + BN_EPS);
        g_sc1[o] = s;
        g_sh1[o] = be1[o] + (b1[o] - m1[o]) * s;
    } else if (i < 8192 + 2048 + 512 + 64 + 32) {
        int o = i - (8192 + 2048 + 512 + 64);
        float s = gg2[o] * rsqrtf(v2[o] + BN_EPS);
        g_sc2[o] = s;
        g_sh2[o] = be2[o] + (b2[o] - m2[o]) * s;
    } else if (i < 8192 + 2048 + 512 + 64 + 32 + 16) {
        int o = i - (8192 + 2048 + 512 + 64 + 32);
        float s = gg3[o] * rsqrtf(v3[o] + BN_EPS);
        g_sc3[o] = s;
        g_sh3[o] = be3[o] + (b3[o] - m3[o]) * s;
    }
}

// ---------------- GEMM: Z{0,1,2} = X @ {Wd, W[1], W[2]}  (sections on grid.y)
// thread tile 4 rows x 8 cols, packed f32x2 accumulators, weights loaded as
// ulonglong2 so (w_even,w_odd) pairs need no repacking.
template <int Fin, int Fout>
__global__ void __launch_bounds__(256)
k_gemm(const float* __restrict__ X, const float* __restrict__ Wd,
       const float* __restrict__ W,
       float* __restrict__ Z0, float* __restrict__ Z1, float* __restrict__ Z2) {
    constexpr int CT   = Fout / 8;
    constexpr int RT   = 256 / CT;
    constexpr int ROWS = RT * 4;
    int ct = threadIdx.x % CT;
    int rt = threadIdx.x / CT;
    int r0 = blockIdx.x * ROWS + rt * 4;
    int o0 = ct * 8;
    int sec = blockIdx.y;
    const float* Wsec = (sec == 0) ? Wd : (W + sec * Fin * Fout);
    float* out = (sec == 0) ? Z0 : ((sec == 1) ? Z1 : Z2);

    int rr[4];
#pragma unroll
    for (int j = 0; j < 4; j++) rr[j] = min(r0 + j, NN - 1);

    unsigned long long acc[4][4];
#pragma unroll
    for (int j = 0; j < 4; j++)
#pragma unroll
        for (int c = 0; c < 4; c++) acc[j][c] = 0ull;

    for (int f0 = 0; f0 < Fin; f0 += 4) {
        float4 h4[4];
#pragma unroll
        for (int j = 0; j < 4; j++)
            h4[j] = *reinterpret_cast<const float4*>(X + rr[j] * Fin + f0);
#pragma unroll
        for (int ff = 0; ff < 4; ff++) {
            const float* wrow = Wsec + (f0 + ff) * Fout + o0;
            ulonglong2 wA = *reinterpret_cast<const ulonglong2*>(wrow);
            ulonglong2 wB = *reinterpret_cast<const ulonglong2*>(wrow + 4);
#pragma unroll
            for (int j = 0; j < 4; j++) {
                float h = reinterpret_cast<const float*>(&h4[j])[ff];
                unsigned long long hd = dup2(h);
                acc[j][0] = ffma2(hd, wA.x, acc[j][0]);
                acc[j][1] = ffma2(hd, wA.y, acc[j][1]);
                acc[j][2] = ffma2(hd, wB.x, acc[j][2]);
                acc[j][3] = ffma2(hd, wB.y, acc[j][3]);
            }
        }
    }

#pragma unroll
    for (int j = 0; j < 4; j++) {
        int row = r0 + j;
        if (row < NN) {
            ulonglong2 p0; p0.x = acc[j][0]; p0.y = acc[j][1];
            ulonglong2 p1; p1.x = acc[j][2]; p1.y = acc[j][3];
            *reinterpret_cast<ulonglong2*>(out + row * Fout + o0)     = p0;
            *reinterpret_cast<ulonglong2*>(out + row * Fout + o0 + 4) = p1;
        }
    }
}

// ---------------- props: one warp per node, multiple edges in flight -------
// subgroup of LPN = F/4 lanes owns one edge (float4 per lane); EPW = 32/LPN
// edges processed in parallel, shuffle-tree merged at the end.

// prop A: S = Z1 + 2 * (L_hat @ Z2)
template <int F>
__global__ void k_propA(const float* __restrict__ X, const float* __restrict__ Z1,
                        float* __restrict__ S) {
    constexpr int LPN = F / 4;
    constexpr int EPW = 32 / LPN;
    int warp = (blockIdx.x * blockDim.x + threadIdx.x) >> 5;
    if (warp >= NN) return;
    int lane = threadIdx.x & 31;
    int sub = lane / LPN, fl = lane % LPN;
    int beg = g_rowptr[warp], end = g_rowptr[warp + 1];

    float4 acc = make_float4(0.f, 0.f, 0.f, 0.f);
    for (int idx = beg + sub; idx < end; idx += EPW) {
        int s    = g_csr_src[idx];
        float wv = g_csr_w[idx];
        float4 xv = *reinterpret_cast<const float4*>(X + s * F + fl * 4);
        acc.x += wv * xv.x; acc.y += wv * xv.y;
        acc.z += wv * xv.z; acc.w += wv * xv.w;
    }
#pragma unroll
    for (int off = 16; off >= LPN; off >>= 1) {
        acc.x += __shfl_down_sync(0xffffffffu, acc.x, off);
        acc.y += __shfl_down_sync(0xffffffffu, acc.y, off);
        acc.z += __shfl_down_sync(0xffffffffu, acc.z, off);
        acc.w += __shfl_down_sync(0xffffffffu, acc.w, off);
    }
    if (sub == 0) {
        float4 z = *reinterpret_cast<const float4*>(Z1 + warp * F + fl * 4);
        float4 o;
        o.x = z.x + 2.f * acc.x; o.y = z.y + 2.f * acc.y;
        o.z = z.z + 2.f * acc.z; o.w = z.w + 2.f * acc.w;
        *reinterpret_cast<float4*>(S + warp * F + fl * 4) = o;
    }
}

// prop B: H = lrelu( (Z0 + L_hat @ S) * scale + shift )
template <int F>
__global__ void k_propB(const float* __restrict__ X, const float* __restrict__ Z0,
                        const float* __restrict__ scale, const float* __restrict__ shift,
                        float* __restrict__ H) {
    constexpr int LPN = F / 4;
    constexpr int EPW = 32 / LPN;
    int warp = (blockIdx.x * blockDim.x + threadIdx.x) >> 5;
    if (warp >= NN) return;
    int lane = threadIdx.x & 31;
    int sub = lane / LPN, fl = lane % LPN;
    int beg = g_rowptr[warp], end = g_rowptr[warp + 1];

    float4 acc = make_float4(0.f, 0.f, 0.f, 0.f);
    for (int idx = beg + sub; idx < end; idx += EPW) {
        int s    = g_csr_src[idx];
        float wv = g_csr_w[idx];
        float4 xv = *reinterpret_cast<const float4*>(X + s * F + fl * 4);
        acc.x += wv * xv.x; acc.y += wv * xv.y;
        acc.z += wv * xv.z; acc.w += wv * xv.w;
    }
#pragma unroll
    for (int off = 16; off >= LPN; off >>= 1) {
        acc.x += __shfl_down_sync(0xffffffffu, acc.x, off);
        acc.y += __shfl_down_sync(0xffffffffu, acc.y, off);
        acc.z += __shfl_down_sync(0xffffffffu, acc.z, off);
        acc.w += __shfl_down_sync(0xffffffffu, acc.w, off);
    }
    if (sub == 0) {
        float4 z  = *reinterpret_cast<const float4*>(Z0 + warp * F + fl * 4);
        float4 sc = *reinterpret_cast<const float4*>(scale + fl * 4);
        float4 sh = *reinterpret_cast<const float4*>(shift + fl * 4);
        float4 o;
        o.x = (z.x + acc.x) * sc.x + sh.x;
        o.y = (z.y + acc.y) * sc.y + sh.y;
        o.z = (z.z + acc.z) * sc.z + sh.z;
        o.w = (z.w + acc.w) * sc.w + sh.w;
        o.x = (o.x > 0.f) ? o.x : SLOPE * o.x;
        o.y = (o.y > 0.f) ? o.y : SLOPE * o.y;
        o.z = (o.z > 0.f) ? o.z : SLOPE * o.z;
        o.w = (o.w > 0.f) ? o.w : SLOPE * o.w;
        *reinterpret_cast<float4*>(H + warp * F + fl * 4) = o;
    }
}

// ---------------- per-graph mean pool + head --------------------------------
#define PNODES 1024
__global__ void k_pool(const float* __restrict__ H, const int* __restrict__ batch) {
    __shared__ float ssum[GG * 16];
    __shared__ int   scnt[GG];
    for (int i = threadIdx.x; i < GG * 16; i += 256) ssum[i] = 0.f;
    for (int i = threadIdx.x; i < GG; i += 256) scnt[i] = 0;
    __syncthreads();

    int f   = threadIdx.x & 15;
    int sub = threadIdx.x >> 4;
    int base = blockIdx.x * PNODES;
    for (int n = sub; n < PNODES; n += 16) {
        int node = base + n;
        if (node >= NN) break;
        int b = batch[node];
        atomicAdd(&ssum[b * 16 + f], H[node * 16 + f]);
        if (f == 0) atomicAdd(&scnt[b], 1);
    }
    __syncthreads();
    for (int i = threadIdx.x; i < GG * 16; i += 256) atomicAdd(&g_pooled[i], ssum[i]);
    for (int i = threadIdx.x; i < GG; i += 256) atomicAdd(&g_pcnt[i], scnt[i]);
}

__global__ void k_final(const float* __restrict__ lw, const float* __restrict__ lb,
                        float* __restrict__ out) {
    int t = threadIdx.x;
    if (t >= GG * 2) return;
    int g = t >> 1, c = t & 1;
    float inv = 1.f / fmaxf((float)g_pcnt[g], 1.f);
    float s = 0.f;
#pragma unroll
    for (int f = 0; f < 16; f++) s += g_pooled[g * 16 + f] * lw[c * 16 + f];
    out[t] = s * inv + lb[c];
}

// ---------------- launch ----------------------------------------------------
extern "C" void kernel_launch(void* const* d_in, const int* in_sizes, int n_in,
                              void* d_out, int out_size) {
    const float* x     = (const float*)d_in[0];
    const int*   ei    = (const int*)  d_in[1];
    const int*   batch = (const int*)  d_in[2];
    const float* W1 = (const float*)d_in[3];
    const float* b1 = (const float*)d_in[4];
    const float* g1 = (const float*)d_in[5];
    const float* be1= (const float*)d_in[6];
    const float* m1 = (const float*)d_in[7];
    const float* v1 = (const float*)d_in[8];
    const float* W2 = (const float*)d_in[9];
    const float* b2 = (const float*)d_in[10];
    const float* g2 = (const float*)d_in[11];
    const float* be2= (const float*)d_in[12];
    const float* m2 = (const float*)d_in[13];
    const float* v2 = (const float*)d_in[14];
    const float* W3 = (const float*)d_in[15];
    const float* b3 = (const float*)d_in[16];
    const float* g3 = (const float*)d_in[17];
    const float* be3= (const float*)d_in[18];
    const float* m3 = (const float*)d_in[19];
    const float* v3 = (const float*)d_in[20];
    const float* lw = (const float*)d_in[21];
    const float* lb = (const float*)d_in[22];
    float* out = (float*)d_out;

    float *Z0, *Z1, *Z2, *S, *H1, *H2, *H3;
    float *Wd1, *Wd2, *Wd3, *sc1, *sh1, *sc2, *sh2, *sc3, *sh3;
    cudaGetSymbolAddress((void**)&Z0, g_Z0);
    cudaGetSymbolAddress((void**)&Z1, g_Z1);
    cudaGetSymbolAddress((void**)&Z2, g_Z2);
    cudaGetSymbolAddress((void**)&S,  g_S);
    cudaGetSymbolAddress((void**)&H1, g_H1);
    cudaGetSymbolAddress((void**)&H2, g_H2);
    cudaGetSymbolAddress((void**)&H3, g_H3);
    cudaGetSymbolAddress((void**)&Wd1, g_Wd1);
    cudaGetSymbolAddress((void**)&Wd2, g_Wd2);
    cudaGetSymbolAddress((void**)&Wd3, g_Wd3);
    cudaGetSymbolAddress((void**)&sc1, g_sc1);
    cudaGetSymbolAddress((void**)&sh1, g_sh1);
    cudaGetSymbolAddress((void**)&sc2, g_sc2);
    cudaGetSymbolAddress((void**)&sh2, g_sh2);
    cudaGetSymbolAddress((void**)&sc3, g_sc3);
    cudaGetSymbolAddress((void**)&sh3, g_sh3);

    const int TB = 256;
    // --- graph normalization + CSR build + weight prep ---
    k_zero <<<(NN + TB - 1) / TB, TB>>>();
    k_count<<<(EE + TB - 1) / TB, TB>>>(ei);
    k_dinv <<<(NN + TB - 1) / TB, TB>>>();
    k_scan1<<<NB_SCAN, 1024>>>();
    k_scan2<<<1, 32>>>(NB_SCAN);
    k_scan3<<<(NN + TB - 1) / TB, TB>>>(NB_SCAN);
    k_fill <<<(EE + TB - 1) / TB, TB>>>(ei);
    k_prep <<<(8192 + 2048 + 512 + 112 + TB - 1) / TB, TB>>>(
        W1, W2, W3, b1, g1, be1, m1, v1, b2, g2, be2, m2, v2, b3, g3, be3, m3, v3);

    int prop_grid = (NN * 32 + TB - 1) / TB;   // one warp per node

    // --- layer 1: 128 -> 64 ---
    k_gemm<128, 64><<<dim3((NN + 127) / 128, 3), 256>>>(x, Wd1, W1, Z0, Z1, Z2);
    k_propA<64><<<prop_grid, TB>>>(Z2, Z1, S);
    k_propB<64><<<prop_grid, TB>>>(S, Z0, sc1, sh1, H1);

    // --- layer 2: 64 -> 32 ---
    k_gemm<64, 32><<<dim3((NN + 255) / 256, 3), 256>>>(H1, Wd2, W2, Z0, Z1, Z2);
    k_propA<32><<<prop_grid, TB>>>(Z2, Z1, S);
    k_propB<32><<<prop_grid, TB>>>(S, Z0, sc2, sh2, H2);

    // --- layer 3: 32 -> 16 ---
    k_gemm<32, 16><<<dim3((NN + 511) / 512, 3), 256>>>(H2, Wd3, W3, Z0, Z1, Z2);
    k_propA<16><<<prop_grid, TB>>>(Z2, Z1, S);
    k_propB<16><<<prop_grid, TB>>>(S, Z0, sc3, sh3, H3);

    // --- pool + linear head ---
    k_pool <<<(NN + PNODES - 1) / PNODES, 256>>>(H3, batch);
    k_final<<<1, 128>>>(lw, lb, out);
}